// round 11
// baseline (speedup 1.0000x reference)
#include <cuda_runtime.h>
#include <cuda_fp16.h>
#include <cuda_fp8.h>
#include <math.h>
#include <cstdint>

// NTXent loss, 2B = 8192, D = 128.
// Symmetric e4m3 QMMA GEMM (m16n8k32, f16 acc) over upper-triangle 128x128
// blocks, strip-mined. Inputs pre-scaled by sqrt(2*log2(e)) so acc == ex2 arg.
// 3 launches: normalize -> gemm -> fused finalize+reduce (last-block).

#define TWO_B   8192
#define DIM     128
#define NBLK    64
#define NCTA    288           // sum over octets o: (8-o)*8
#define NSLOT   72            // 8 row-sum slots + 64 col-sum slots
#define NFBLK   32            // finalize blocks

__device__ uint8_t g_X8[TWO_B * DIM];           // normalized*sqrt(C2) e4m3 (MMA)
__device__ float   g_inorm[TWO_B];              // 1/||e_i||
__device__ float   g_part[NSLOT][TWO_B];        // [slot][row] partials (unused stay 0)
__device__ float   g_bpart[NFBLK];              // per-block loss partials
__device__ int     g_count;                     // last-block counter (self-resetting)

// C2 = 2*log2(e); SQC2 = sqrt(C2)
#define SQC2 1.6986435838704467f

// ---------------------------------------------------------------------------
// helpers
// ---------------------------------------------------------------------------
__device__ __forceinline__ uint32_t smem_u32(const void* p) {
    uint32_t a;
    asm("{ .reg .u64 t; cvta.to.shared.u64 t, %1; cvt.u32.u64 %0, t; }" : "=r"(a) : "l"(p));
    return a;
}
__device__ __forceinline__ void cp16(uint32_t saddr, const void* g) {
    asm volatile("cp.async.cg.shared.global [%0], [%1], 16;" :: "r"(saddr), "l"(g));
}
#define CP_COMMIT() asm volatile("cp.async.commit_group;" ::: "memory")
#define CP_WAIT0()  asm volatile("cp.async.wait_group 0;" ::: "memory")

__device__ __forceinline__ void ldsm4(uint32_t* r, uint32_t addr) {
    asm volatile("ldmatrix.sync.aligned.m8n8.x4.shared.b16 {%0,%1,%2,%3}, [%4];"
                 : "=r"(r[0]), "=r"(r[1]), "=r"(r[2]), "=r"(r[3]) : "r"(addr));
}
// e4m3 QMMA, f16 accumulators: D,C = 2 b32 regs
__device__ __forceinline__ void mma16832q(uint32_t* d, const uint32_t* a, uint32_t b0, uint32_t b1) {
    asm volatile("mma.sync.aligned.m16n8k32.row.col.f16.e4m3.e4m3.f16 "
                 "{%0,%1}, {%2,%3,%4,%5}, {%6,%7}, {%0,%1};"
                 : "+r"(d[0]), "+r"(d[1])
                 : "r"(a[0]), "r"(a[1]), "r"(a[2]), "r"(a[3]), "r"(b0), "r"(b1));
}
__device__ __forceinline__ uint32_t hex2(uint32_t x) {
    uint32_t y; asm("ex2.approx.f16x2 %0, %1;" : "=r"(y) : "r"(x)); return y;
}
__device__ __forceinline__ uint32_t hadd2(uint32_t a, uint32_t b) {
    uint32_t y; asm("add.rn.f16x2 %0, %1, %2;" : "=r"(y) : "r"(a), "r"(b)); return y;
}
__device__ __forceinline__ float2 h2f(uint32_t r) {
    __half2 h = *reinterpret_cast<__half2*>(&r);
    return __half22float2(h);
}
__device__ __forceinline__ float ex2f(float x) {
    float y; asm("ex2.approx.ftz.f32 %0, %1;" : "=f"(y) : "f"(x)); return y;
}

// ---------------------------------------------------------------------------
// 1) Row-normalize -> scaled e4m3 + inverse norms. One warp per row.
// ---------------------------------------------------------------------------
__global__ void __launch_bounds__(256) normalize_kernel(const float* __restrict__ E) {
    int warp = threadIdx.x >> 5, lane = threadIdx.x & 31;
    int row = blockIdx.x * 8 + warp;
    const float4 v = *reinterpret_cast<const float4*>(&E[row * DIM + lane * 4]);
    float ss = v.x * v.x + v.y * v.y + v.z * v.z + v.w * v.w;
    #pragma unroll
    for (int o = 16; o > 0; o >>= 1) ss += __shfl_xor_sync(0xffffffffu, ss, o);
    float inv = rsqrtf(fmaxf(ss, 1e-24f));
    if (lane == 0) g_inorm[row] = inv;
    float s = inv * SQC2;
    __nv_fp8x2_storage_t p0 = __nv_cvt_float2_to_fp8x2(
        make_float2(v.x * s, v.y * s), __NV_SATFINITE, __NV_E4M3);
    __nv_fp8x2_storage_t p1 = __nv_cvt_float2_to_fp8x2(
        make_float2(v.z * s, v.w * s), __NV_SATFINITE, __NV_E4M3);
    uint32_t pk = (uint32_t)p0 | ((uint32_t)p1 << 16);
    *reinterpret_cast<uint32_t*>(&g_X8[row * DIM + lane * 4]) = pk;
}

// ---------------------------------------------------------------------------
// 2) Strip-mined symmetric e4m3 QMMA GEMM + exp row/col sums.
//    256 threads = 8 warps (wm 0..3 x wn 0..1); warp tile 32x64; K=128 (4 k32).
// ---------------------------------------------------------------------------
#define SROWB   144                        // smem row stride (9*16 B), 128B data
#define TILE_B  (128 * SROWB)              // 18432
#define SM_A    0
#define SM_B0   TILE_B
#define SM_B1   (2 * TILE_B)
#define SM_RED  (3 * TILE_B)               // colred[4][128] / rowred[2][128]
#define SM_TOT  (SM_RED + 4 * 128 * 4)     // 57344

__global__ void __launch_bounds__(256, 3) gemm_sym_kernel() {
    extern __shared__ __align__(16) char smem[];
    const uint32_t sb = smem_u32(smem);
    const int tid  = threadIdx.x;
    const int lane = tid & 31;
    const int warp = tid >> 5;
    const int wm = warp >> 1;              // 0..3
    const int wn = warp & 1;               // 0..1

    // decode blockIdx -> (I, c): octet o of I, chunks c = o..7
    int t = blockIdx.x, o = 0;
    for (;;) { int n = (8 - o) * 8; if (t < n) break; t -= n; ++o; }
    const int c  = o + (t >> 3);
    const int I  = 8 * o + (t & 7);
    const int J0 = max(8 * c, I);
    const int L  = 8 * c + 8 - J0;         // strip length (1..8)
    const int rowBase = I * 128;

    const char* __restrict__ Xb = reinterpret_cast<const char*>(g_X8);

    // cooperative 16KB tile load (128 rows x 128B)
    auto loadTile = [&](uint32_t dst, int gRow) {
        #pragma unroll
        for (int i = 0; i < 4; ++i) {
            int f = tid + i * 256;          // 0..1023 16B-chunks
            int r = f >> 3, cc = (f & 7) << 4;
            cp16(dst + r * SROWB + cc, Xb + (size_t)(gRow + r) * 128 + cc);
        }
    };

    loadTile(sb + SM_A, rowBase);
    loadTile(sb + SM_B0, J0 * 128);
    CP_COMMIT();

    const uint32_t aBase = sb + SM_A + (uint32_t)(wm * 32 + (lane & 15)) * SROWB + ((lane >> 4) << 4);
    const uint32_t bOff  = (uint32_t)(wn * 64 + (lane & 15)) * SROWB + ((lane >> 4) << 4);

    float rs32[4] = {0.f, 0.f, 0.f, 0.f};  // strip row sums (fp32)
    float* colred = reinterpret_cast<float*>(smem + SM_RED);   // [4][128]

    for (int k = 0; k < L; ++k) {
        const int J = J0 + k;
        CP_WAIT0();
        __syncthreads();   // B(k) resident; prev tile's colred reads done

        if (k + 1 < L) {
            loadTile(sb + (((k + 1) & 1) ? SM_B1 : SM_B0), (J + 1) * 128);
            CP_COMMIT();
        }

        const uint32_t bBase = sb + ((k & 1) ? SM_B1 : SM_B0) + bOff;

        uint32_t acc[2][8][2];             // f16x2 accumulators
        #pragma unroll
        for (int m = 0; m < 2; ++m)
            #pragma unroll
            for (int n = 0; n < 8; ++n) { acc[m][n][0] = 0u; acc[m][n][1] = 0u; }

        #pragma unroll
        for (int ks = 0; ks < 4; ++ks) {   // 4 k-steps of K=32 fp8 (32B)
            uint32_t a[2][4], b[4][4];
            #pragma unroll
            for (int m = 0; m < 2; ++m)
                ldsm4(a[m], aBase + m * (16 * SROWB) + ks * 32);
            #pragma unroll
            for (int n4 = 0; n4 < 4; ++n4)
                ldsm4(b[n4], bBase + n4 * (16 * SROWB) + ks * 32);
            #pragma unroll
            for (int m = 0; m < 2; ++m)
                #pragma unroll
                for (int n4 = 0; n4 < 4; ++n4) {
                    mma16832q(acc[m][n4 * 2 + 0], a[m], b[n4][0], b[n4][2]);
                    mma16832q(acc[m][n4 * 2 + 1], a[m], b[n4][1], b[n4][3]);
                }
        }

        // epilogue: packed e = ex2(acc); row sums + column sums
        uint32_t cs[8];
        #pragma unroll
        for (int n = 0; n < 8; ++n) cs[n] = 0u;

        #pragma unroll
        for (int m = 0; m < 2; ++m) {
            uint32_t rsp[2] = {0u, 0u};
            #pragma unroll
            for (int n = 0; n < 8; ++n) {
                uint32_t e0 = hex2(acc[m][n][0]);
                uint32_t e1 = hex2(acc[m][n][1]);
                rsp[0] = hadd2(rsp[0], e0);
                rsp[1] = hadd2(rsp[1], e1);
                cs[n] = hadd2(cs[n], hadd2(e0, e1));
            }
            #pragma unroll
            for (int g = 0; g < 2; ++g) {
                float2 f = h2f(rsp[g]);
                rs32[m * 2 + g] += f.x + f.y;
            }
        }

        if (J != I) {
            #pragma unroll
            for (int n = 0; n < 8; ++n) {
                cs[n] = hadd2(cs[n], __shfl_xor_sync(0xffffffffu, cs[n], 4));
                cs[n] = hadd2(cs[n], __shfl_xor_sync(0xffffffffu, cs[n], 8));
                cs[n] = hadd2(cs[n], __shfl_xor_sync(0xffffffffu, cs[n], 16));
            }
            if (lane < 4) {
                #pragma unroll
                for (int n = 0; n < 8; ++n) {
                    int cc = wn * 64 + (n >> 1) * 16 + (n & 1) * 8 + lane * 2;
                    float2 f = h2f(cs[n]);
                    *reinterpret_cast<float2*>(&colred[wm * 128 + cc]) = f;
                }
            }
            __syncthreads();
            if (tid < 128) {
                float ct = colred[tid] + colred[128 + tid] +
                           colred[256 + tid] + colred[384 + tid];
                g_part[8 + I][J * 128 + tid] = ct;
            }
        } else {
            __syncthreads();   // keep barrier count uniform
        }
    }

    // strip row sums
    #pragma unroll
    for (int u = 0; u < 4; ++u) {
        rs32[u] += __shfl_xor_sync(0xffffffffu, rs32[u], 1);
        rs32[u] += __shfl_xor_sync(0xffffffffu, rs32[u], 2);
    }
    float* rowred = reinterpret_cast<float*>(smem + SM_RED);   // [2][128]
    __syncthreads();
    if ((lane & 3) == 0) {
        #pragma unroll
        for (int u = 0; u < 4; ++u) {
            int r = wm * 32 + (u >> 1) * 16 + (u & 1) * 8 + (lane >> 2);
            rowred[wn * 128 + r] = rs32[u];
        }
    }
    __syncthreads();
    if (tid < 128)
        g_part[c][rowBase + tid] = rowred[tid] + rowred[128 + tid];
}

// ---------------------------------------------------------------------------
// 3) Fused finalize + reduce. 32 blocks x 256 threads, one row per thread.
// ---------------------------------------------------------------------------
__global__ void __launch_bounds__(256) finalize_reduce_kernel(
        const float* __restrict__ E, const int* __restrict__ labels,
        float* __restrict__ out) {
    const int i = blockIdx.x * 256 + threadIdx.x;

    float R = 0.f;
    #pragma unroll 8
    for (int s = 0; s < NSLOT; ++s) R += g_part[s][i];

    int pos = (i < TWO_B / 2) ? (i + TWO_B / 2) : (i - TWO_B / 2);
    int a = min(i, pos), b = max(i, pos);
    int l = labels[i];
    int j = l + (l >= a ? 1 : 0);
    j += (j >= b ? 1 : 0);

    // exact fp32 picked logit from raw E + inverse norms
    const float* ei = E + (size_t)i * DIM;
    const float* ej = E + (size_t)j * DIM;
    float dq = 0.f;
    #pragma unroll
    for (int k = 0; k < DIM; k += 4) {
        float4 vi = *reinterpret_cast<const float4*>(&ei[k]);
        float4 vj = *reinterpret_cast<const float4*>(&ej[k]);
        dq += vi.x * vj.x + vi.y * vj.y + vi.z * vj.z + vi.w * vj.w;
    }
    float q = 2.0f * dq * g_inorm[i] * g_inorm[j];

    // fp8-consistent diagonal + positive-pair terms (scaled: acc == ex2 arg)
    float dii = 0.f, dpp = 0.f;
    const uint8_t* hi = g_X8 + (size_t)i   * DIM;
    const uint8_t* hp = g_X8 + (size_t)pos * DIM;
    #pragma unroll 4
    for (int k = 0; k < DIM; ++k) {
        float xa = (float)*reinterpret_cast<const __nv_fp8_e4m3*>(&hi[k]);
        float xb = (float)*reinterpret_cast<const __nv_fp8_e4m3*>(&hp[k]);
        dii += xa * xa;
        dpp += xa * xb;
    }

    float masked = R - ex2f(dii) - ex2f(dpp);
    float loss = logf(masked) - q;

    // block reduce (deterministic) + last-block combine
    __shared__ float sm[256];
    __shared__ bool isLast;
    sm[threadIdx.x] = loss;
    __syncthreads();
    #pragma unroll
    for (int off = 128; off > 0; off >>= 1) {
        if (threadIdx.x < off) sm[threadIdx.x] += sm[threadIdx.x + off];
        __syncthreads();
    }
    if (threadIdx.x == 0) {
        g_bpart[blockIdx.x] = sm[0];
        __threadfence();
        int cdone = atomicAdd(&g_count, 1);
        isLast = (cdone == NFBLK - 1);
    }
    __syncthreads();
    if (isLast && threadIdx.x == 0) {
        float s = 0.f;
        #pragma unroll
        for (int bb = 0; bb < NFBLK; ++bb) s += g_bpart[bb];
        out[0] = s / (float)TWO_B;
        g_count = 0;                      // reset for next graph replay
    }
}

// ---------------------------------------------------------------------------
extern "C" void kernel_launch(void* const* d_in, const int* in_sizes, int n_in,
                              void* d_out, int out_size) {
    const float* E      = (const float*)d_in[0];
    const int*   labels = (const int*)d_in[1];
    float* out = (float*)d_out;

    cudaFuncSetAttribute(gemm_sym_kernel,
                         cudaFuncAttributeMaxDynamicSharedMemorySize, SM_TOT);

    normalize_kernel<<<TWO_B / 8, 256>>>(E);
    gemm_sym_kernel<<<NCTA, 256, SM_TOT>>>();
    finalize_reduce_kernel<<<NFBLK, 256>>>(E, labels, out);
}